// round 15
// baseline (speedup 1.0000x reference)
#include <cuda_runtime.h>
#include <math.h>
#include <stdint.h>

// Problem constants
#define B 512
#define V 6890
#define J 24
#define NB 10
#define P 207           // (J-1)*9
#define N3 (V*3)        // 20670
#define KT 224          // padded GEMM K: 207 posedirs + 10 shapedirs + 7 zero
#define VS 20736        // padded column stride

__constant__ int c_parents[J] = {0,0,0,0,1,2,3,4,5,6,7,8,9,9,9,12,13,14,16,17,18,19,20,21};

// Scratch (device globals)
__device__ float g_jt[J*3];
__device__ float g_JS[J*3*NB];
__device__ float g_AT[KT*B];                // A^T (tf32-rounded): [k][b]
__device__ float g_rel[B*J*12];             // rel transforms, 3x4 row-major
__device__ float g_vposed[(size_t)B*VS];    // v_shaped + pose correction (padded)

__device__ __forceinline__ float tf32r(float x) {
    uint32_t y; asm("cvt.rna.tf32.f32 %0, %1;" : "=r"(y) : "f"(x));
    return __uint_as_float(y);
}

#define MMA_TF32(acc, a0,a1,a2,a3, b0,b1) \
    asm volatile( \
        "mma.sync.aligned.m16n8k8.row.col.f32.tf32.tf32.f32 " \
        "{%0,%1,%2,%3}, {%4,%5,%6,%7}, {%8,%9}, {%0,%1,%2,%3};\n" \
        : "+f"(acc[0]), "+f"(acc[1]), "+f"(acc[2]), "+f"(acc[3]) \
        : "r"(a0), "r"(a1), "r"(a2), "r"(a3), "r"(b0), "r"(b1))

__device__ __forceinline__ void cp_async16(uint32_t saddr, const void* gptr) {
    asm volatile("cp.async.cg.shared.global [%0], [%1], 16;" :: "r"(saddr), "l"(gptr));
}
__device__ __forceinline__ void cp_async8(uint32_t saddr, const void* gptr) {
    asm volatile("cp.async.ca.shared.global [%0], [%1], 8;" :: "r"(saddr), "l"(gptr));
}
#define CP_COMMIT() asm volatile("cp.async.commit_group;" ::: "memory")
#define CP_WAIT1()  asm volatile("cp.async.wait_group 1;" ::: "memory")
#define CP_WAIT0()  asm volatile("cp.async.wait_group 0;" ::: "memory")

// ---------------------------------------------------------------------------
// K1: jt / JS regression (tiny)
// ---------------------------------------------------------------------------
__global__ void k1_regress(const float* __restrict__ Jreg,
                           const float* __restrict__ vt,
                           const float* __restrict__ sd) {
    int j = blockIdx.x;
    int q = blockIdx.y;
    int tid = threadIdx.x;
    const float* jr = Jreg + (size_t)j * V;
    float acc = 0.f;
    if (q < 3) {
        for (int v = tid; v < V; v += 256) acc += jr[v] * vt[v*3 + q];
    } else {
        int kl = q - 3;
        for (int v = tid; v < V; v += 256) acc += jr[v] * sd[v*30 + kl];
    }
    __shared__ float red[256];
    red[tid] = acc;
    __syncthreads();
    for (int s = 128; s > 0; s >>= 1) {
        if (tid < s) red[tid] += red[tid + s];
        __syncthreads();
    }
    if (tid == 0) {
        if (q < 3) g_jt[j*3 + q] = red[0];
        else       g_JS[j*30 + (q-3)] = red[0];
    }
}

// ---------------------------------------------------------------------------
// K2: rodrigues + chain + rel transforms; fills tf32-rounded g_AT.
// ---------------------------------------------------------------------------
__global__ void k2_pose(const float* __restrict__ ro,
                        const float* __restrict__ pb,
                        const float* __restrict__ ph,
                        const float* __restrict__ betas,
                        const float* __restrict__ trans,
                        float* __restrict__ out_joints) {
    int b = blockIdx.x;
    int lane = threadIdx.x;

    __shared__ float rot[J][9];
    __shared__ float jnt[J][3];
    __shared__ float G[J][12];

    if (lane < J) {
        float r0, r1, r2;
        if (lane == 0)        { const float* p = ro + b*3;                 r0=p[0]; r1=p[1]; r2=p[2]; }
        else if (lane <= 21)  { const float* p = pb + b*63 + (lane-1)*3;   r0=p[0]; r1=p[1]; r2=p[2]; }
        else                  { const float* p = ph + b*6  + (lane-22)*3;  r0=p[0]; r1=p[1]; r2=p[2]; }

        float a2  = r0*r0 + r1*r1 + r2*r2 + 1e-8f;
        float ang = sqrtf(a2);
        float inv = 1.f / ang;
        float x = r0*inv, y = r1*inv, z = r2*inv;
        float c = cosf(ang), s = sinf(ang), o = 1.f - c;

        float R[9];
        R[0] = c + o*x*x;     R[1] = -s*z + o*x*y;  R[2] =  s*y + o*x*z;
        R[3] =  s*z + o*y*x;  R[4] = c + o*y*y;     R[5] = -s*x + o*y*z;
        R[6] = -s*y + o*z*x;  R[7] =  s*x + o*z*y;  R[8] = c + o*z*z;

        #pragma unroll
        for (int e = 0; e < 9; e++) rot[lane][e] = R[e];

        if (lane >= 1) {
            int base = (lane-1)*9;
            #pragma unroll
            for (int e = 0; e < 9; e++)
                g_AT[(base+e)*B + b] = tf32r(R[e] - ((e == 0 || e == 4 || e == 8) ? 1.f : 0.f));
        }

        float bt[NB];
        #pragma unroll
        for (int l = 0; l < NB; l++) bt[l] = betas[b*NB + l];
        #pragma unroll
        for (int k = 0; k < 3; k++) {
            float a = g_jt[lane*3 + k];
            #pragma unroll
            for (int l = 0; l < NB; l++) a += bt[l] * g_JS[lane*30 + k*10 + l];
            jnt[lane][k] = a;
        }
    }
    if (lane < NB)  g_AT[(P + lane)*B + b] = tf32r(betas[b*NB + lane]);
    if (lane >= 25) g_AT[(192 + lane)*B + b] = 0.f;   // rows 217..223
    __syncthreads();

    if (lane == 0) {
        #pragma unroll
        for (int m = 0; m < 3; m++) {
            G[0][m*4+0] = rot[0][m*3+0];
            G[0][m*4+1] = rot[0][m*3+1];
            G[0][m*4+2] = rot[0][m*3+2];
            G[0][m*4+3] = jnt[0][m];
        }
        for (int j = 1; j < J; j++) {
            int p = c_parents[j];
            float t0 = jnt[j][0] - jnt[p][0];
            float t1 = jnt[j][1] - jnt[p][1];
            float t2 = jnt[j][2] - jnt[p][2];
            #pragma unroll
            for (int m = 0; m < 3; m++) {
                float p0 = G[p][m*4+0], p1 = G[p][m*4+1], p2 = G[p][m*4+2], p3 = G[p][m*4+3];
                G[j][m*4+0] = p0*rot[j][0] + p1*rot[j][3] + p2*rot[j][6];
                G[j][m*4+1] = p0*rot[j][1] + p1*rot[j][4] + p2*rot[j][7];
                G[j][m*4+2] = p0*rot[j][2] + p1*rot[j][5] + p2*rot[j][8];
                G[j][m*4+3] = p0*t0 + p1*t1 + p2*t2 + p3;
            }
        }
    }
    __syncthreads();

    if (lane < J) {
        int j = lane;
        float tx = trans[b*3+0], ty = trans[b*3+1], tz = trans[b*3+2];
        float* oj = out_joints + ((size_t)b*J + j)*3;
        oj[0] = G[j][3]  + tx;
        oj[1] = G[j][7]  + ty;
        oj[2] = G[j][11] + tz;

        float* rl = g_rel + ((size_t)b*J + j)*12;
        #pragma unroll
        for (int m = 0; m < 3; m++) {
            float corr = G[j][m*4+0]*jnt[j][0] + G[j][m*4+1]*jnt[j][1] + G[j][m*4+2]*jnt[j][2];
            rl[m*4+0] = G[j][m*4+0];
            rl[m*4+1] = G[j][m*4+1];
            rl[m*4+2] = G[j][m*4+2];
            rl[m*4+3] = G[j][m*4+3] - corr;
        }
    }
}

// ---------------------------------------------------------------------------
// K3: TF32 GEMM, 3-stage cp.async pipeline, dynamic smem (52,224 B > 48 KB
// static limit). A via cp.async 16B (g_AT rows 16B-aligned); B via 4x
// cp.async 8B for posedirs rows (k*N3 only 8B-aligned for odd k); register
// path for shapedirs/zero rows and the ragged last column block.
// ---------------------------------------------------------------------------
#define BK3 16
#define SST 136
#define NSTG 3
#define K3_SMEM (NSTG * 2 * BK3 * SST * 4)
__global__ void __launch_bounds__(256) k3_tf32(const float* __restrict__ vt,
                                               const float* __restrict__ posedirs,
                                               const float* __restrict__ sd) {
    extern __shared__ float smem3[];
    float (*sA)[BK3][SST] = reinterpret_cast<float (*)[BK3][SST]>(smem3);
    float (*sB)[BK3][SST] = reinterpret_cast<float (*)[BK3][SST]>(smem3 + NSTG*BK3*SST);

    int tid  = threadIdx.x;
    int warp = tid >> 5, lane = tid & 31;
    int wm = warp >> 2;
    int wn = warp & 3;
    int gr = lane >> 2;
    int tg = lane & 3;

    int c0 = blockIdx.x * 128;
    int b0 = blockIdx.y * 128;

    int lk = tid >> 4;           // 0..15 (row within stage)
    int lc = (tid & 15) * 8;     // 0..120

    const int NST = KT / BK3;    // 14

    // Per-thread issue of one stage's loads (A: 8 floats, B: 8 floats)
    auto issue_stage = [&](int st) {
        int buf = st % NSTG;
        int k = st * BK3 + lk;
        uint32_t sa = (uint32_t)__cvta_generic_to_shared(&sA[buf][lk][lc]);
        cp_async16(sa,      g_AT + (size_t)k*B + b0 + lc);
        cp_async16(sa + 16, g_AT + (size_t)k*B + b0 + lc + 4);
        int cbase = c0 + lc;
        if (k < P && cbase + 8 <= N3) {
            uint32_t sb = (uint32_t)__cvta_generic_to_shared(&sB[buf][lk][lc]);
            const float* gp = posedirs + (size_t)k*N3 + cbase;
            cp_async8(sb,      gp);
            cp_async8(sb + 8,  gp + 2);
            cp_async8(sb + 16, gp + 4);
            cp_async8(sb + 24, gp + 6);
        } else {
            // register path: shapedirs rows / zero rows / ragged column block
            #pragma unroll
            for (int i = 0; i < 8; i++) {
                int c = cbase + i;
                float val = 0.f;
                if (c < N3) {
                    if (k < P)           val = posedirs[(size_t)k*N3 + c];
                    else if (k < P + NB) val = sd[(size_t)c*NB + (k - P)];
                }
                sB[buf][lk][lc + i] = val;
            }
        }
    };

    float acc[4][4][4];
    #pragma unroll
    for (int mi = 0; mi < 4; mi++)
        #pragma unroll
        for (int ni = 0; ni < 4; ni++)
            #pragma unroll
            for (int r = 0; r < 4; r++) acc[mi][ni][r] = 0.f;

    // Prologue: stages 0 and 1 in flight
    issue_stage(0); CP_COMMIT();
    issue_stage(1); CP_COMMIT();

    for (int st = 0; st < NST; st++) {
        if (st == NST - 1) { CP_WAIT0(); } else { CP_WAIT1(); }
        __syncthreads();   // stage st resident; also retires reads of buf (st-1)%3
        int buf = st % NSTG;

        #pragma unroll
        for (int ks = 0; ks < 2; ks++) {
            int kb = ks * 8;
            uint32_t bfr[4][2];
            #pragma unroll
            for (int ni = 0; ni < 4; ni++) {
                int n = wn*32 + ni*8 + gr;
                bfr[ni][0] = __float_as_uint(sB[buf][kb + tg][n]);
                bfr[ni][1] = __float_as_uint(sB[buf][kb + tg + 4][n]);
            }
            uint32_t afr[4][4];
            #pragma unroll
            for (int mi = 0; mi < 4; mi++) {
                int m = wm*64 + mi*16 + gr;
                afr[mi][0] = __float_as_uint(sA[buf][kb + tg][m]);
                afr[mi][1] = __float_as_uint(sA[buf][kb + tg][m + 8]);
                afr[mi][2] = __float_as_uint(sA[buf][kb + tg + 4][m]);
                afr[mi][3] = __float_as_uint(sA[buf][kb + tg + 4][m + 8]);
            }
            #pragma unroll
            for (int mi = 0; mi < 4; mi++)
                #pragma unroll
                for (int ni = 0; ni < 4; ni++)
                    MMA_TF32(acc[mi][ni], afr[mi][0], afr[mi][1], afr[mi][2], afr[mi][3],
                             bfr[ni][0], bfr[ni][1]);
        }

        if (st + 2 < NST) {
            issue_stage(st + 2);
            CP_COMMIT();
        }
    }

    // Epilogue: + v_template (fp32), store padded vposed (float2)
    #pragma unroll
    for (int mi = 0; mi < 4; mi++) {
        #pragma unroll
        for (int half = 0; half < 2; half++) {
            int b = b0 + wm*64 + mi*16 + gr + half*8;
            #pragma unroll
            for (int ni = 0; ni < 4; ni++) {
                int c = c0 + wn*32 + ni*8 + tg*2;
                float v0 = (c     < N3) ? vt[c]     : 0.f;
                float v1 = (c + 1 < N3) ? vt[c + 1] : 0.f;
                float2 o = make_float2(acc[mi][ni][half*2]     + v0,
                                       acc[mi][ni][half*2 + 1] + v1);
                *reinterpret_cast<float2*>(g_vposed + (size_t)b*VS + c) = o;
            }
        }
    }
}

// ---------------------------------------------------------------------------
// K4: scalar skinning (measured 62.1us, regs 80, fma 48% = scalar ceiling).
// out = trans + sum_j w[v,j] * (R_j*vp + t_j); 4 verts/lane; rel in smem.
// ---------------------------------------------------------------------------
__global__ void __launch_bounds__(256) k4_skin(const float* __restrict__ weights,
                                               const float* __restrict__ trans,
                                               float* __restrict__ out) {
    int tid = threadIdx.x;        // 256 = 8 warps
    int warp = tid >> 5;
    int lane = tid & 31;
    int b = blockIdx.y * 8 + warp;

    __shared__ float4 s_rel[8][J*3];
    {
        const float4* src = reinterpret_cast<const float4*>(g_rel);
        for (int i = tid; i < 8*J*3; i += 256) {
            int bl = i / (J*3), e = i % (J*3);
            s_rel[bl][e] = src[(size_t)(blockIdx.y*8 + bl)*(J*3) + e];
        }
    }
    __syncthreads();

    float t0 = trans[b*3+0], t1 = trans[b*3+1], t2 = trans[b*3+2];
    const float4* rel = s_rel[warp];
    const size_t bbase = (size_t)b * VS;

    int v0 = blockIdx.x * 128;
    int v[4]; bool ok[4];
    float vx[4], vy[4], vz[4], ox[4], oy[4], oz[4];
    #pragma unroll
    for (int u = 0; u < 4; u++) {
        int vv = v0 + u*32 + lane;
        ok[u] = vv < V;
        v[u] = ok[u] ? vv : (V - 1);
        vx[u] = g_vposed[bbase + v[u]*3 + 0];
        vy[u] = g_vposed[bbase + v[u]*3 + 1];
        vz[u] = g_vposed[bbase + v[u]*3 + 2];
        ox[u] = t0; oy[u] = t1; oz[u] = t2;
    }

    const float4* wv0 = reinterpret_cast<const float4*>(weights + (size_t)v[0]*J);
    const float4* wv1 = reinterpret_cast<const float4*>(weights + (size_t)v[1]*J);
    const float4* wv2 = reinterpret_cast<const float4*>(weights + (size_t)v[2]*J);
    const float4* wv3 = reinterpret_cast<const float4*>(weights + (size_t)v[3]*J);

    #pragma unroll
    for (int q = 0; q < 6; q++) {
        float4 w[4];
        w[0] = wv0[q]; w[1] = wv1[q]; w[2] = wv2[q]; w[3] = wv3[q];
        #pragma unroll
        for (int jj = 0; jj < 4; jj++) {
            int j = q*4 + jj;
            float4 r0 = rel[j*3 + 0];
            float4 r1 = rel[j*3 + 1];
            float4 r2 = rel[j*3 + 2];
            #pragma unroll
            for (int u = 0; u < 4; u++) {
                float wj = (jj == 0) ? w[u].x : (jj == 1) ? w[u].y : (jj == 2) ? w[u].z : w[u].w;
                float rx = fmaf(r0.x, vx[u], fmaf(r0.y, vy[u], fmaf(r0.z, vz[u], r0.w)));
                float ry = fmaf(r1.x, vx[u], fmaf(r1.y, vy[u], fmaf(r1.z, vz[u], r1.w)));
                float rz = fmaf(r2.x, vx[u], fmaf(r2.y, vy[u], fmaf(r2.z, vz[u], r2.w)));
                ox[u] = fmaf(wj, rx, ox[u]);
                oy[u] = fmaf(wj, ry, oy[u]);
                oz[u] = fmaf(wj, rz, oz[u]);
            }
        }
    }

    #pragma unroll
    for (int u = 0; u < 4; u++) {
        if (ok[u]) {
            float* o = out + ((size_t)b*V + v[u])*3;
            o[0] = ox[u]; o[1] = oy[u]; o[2] = oz[u];
        }
    }
}

// ---------------------------------------------------------------------------
extern "C" void kernel_launch(void* const* d_in, const int* in_sizes, int n_in,
                              void* d_out, int out_size) {
    const float* root_orient = (const float*)d_in[0];
    const float* pose_body   = (const float*)d_in[1];
    const float* pose_hand   = (const float*)d_in[2];
    const float* betas       = (const float*)d_in[3];
    const float* trans       = (const float*)d_in[4];
    const float* v_template  = (const float*)d_in[5];
    const float* shapedirs   = (const float*)d_in[6];
    const float* posedirs    = (const float*)d_in[7];
    const float* J_regressor = (const float*)d_in[8];
    const float* weights     = (const float*)d_in[9];

    float* out = (float*)d_out;
    float* out_joints = out + (size_t)B * V * 3;

    // Opt-in to >48KB dynamic smem for k3 (immediate host-side attribute set;
    // not a stream op, so graph capture is unaffected; idempotent).
    cudaFuncSetAttribute(k3_tf32, cudaFuncAttributeMaxDynamicSharedMemorySize, K3_SMEM);

    k1_regress<<<dim3(J, 33), 256>>>(J_regressor, v_template, shapedirs);
    k2_pose<<<B, 32>>>(root_orient, pose_body, pose_hand, betas, trans, out_joints);
    k3_tf32<<<dim3(VS/128, B/128), 256, K3_SMEM>>>(v_template, posedirs, shapedirs);
    k4_skin<<<dim3((V + 127)/128, B/8), 256>>>(weights, trans, out);
}

// round 17
// speedup vs baseline: 1.1032x; 1.1032x over previous
#include <cuda_runtime.h>
#include <math.h>
#include <stdint.h>

// Problem constants
#define B 512
#define V 6890
#define J 24
#define NB 10
#define P 207           // (J-1)*9
#define N3 (V*3)        // 20670
#define KT 224          // padded GEMM K: 207 posedirs + 10 shapedirs + 7 zero
#define VS 20736        // padded column stride

__constant__ int c_parents[J] = {0,0,0,0,1,2,3,4,5,6,7,8,9,9,9,12,13,14,16,17,18,19,20,21};

// Scratch (device globals)
__device__ float g_jt[J*3];
__device__ float g_JS[J*3*NB];
__device__ float g_AT[KT*B];                // A^T (tf32-rounded): [k][b]
__device__ float g_rel[B*J*12];             // rel transforms, 3x4 row-major
__device__ float g_vposed[(size_t)B*VS];    // v_shaped + pose correction (padded)

__device__ __forceinline__ float tf32r(float x) {
    uint32_t y; asm("cvt.rna.tf32.f32 %0, %1;" : "=r"(y) : "f"(x));
    return __uint_as_float(y);
}

#define MMA_TF32(acc, a0,a1,a2,a3, b0,b1) \
    asm volatile( \
        "mma.sync.aligned.m16n8k8.row.col.f32.tf32.tf32.f32 " \
        "{%0,%1,%2,%3}, {%4,%5,%6,%7}, {%8,%9}, {%0,%1,%2,%3};\n" \
        : "+f"(acc[0]), "+f"(acc[1]), "+f"(acc[2]), "+f"(acc[3]) \
        : "r"(a0), "r"(a1), "r"(a2), "r"(a3), "r"(b0), "r"(b1))

// ---------------------------------------------------------------------------
// K0: zero the k1 accumulators (k1 uses atomicAdd).
// ---------------------------------------------------------------------------
__global__ void k0_zero() {
    int tid = blockIdx.x * 256 + threadIdx.x;
    if (tid < J*3)  g_jt[tid] = 0.f;
    if (tid < J*30) g_JS[tid] = 0.f;
}

// ---------------------------------------------------------------------------
// K1: jt/JS regression, read-once layout.
// grid (J, 8): block (j, c) covers a V-chunk, accumulates all 33 outputs
// (3 jt + 30 JS) in registers reading jr once and sd with full-line
// consumption (30 consecutive floats per vertex), then atomicAdd.
// ---------------------------------------------------------------------------
#define VCHUNK 862   // ceil(V/8)
__global__ void __launch_bounds__(256) k1_regress(const float* __restrict__ Jreg,
                                                  const float* __restrict__ vt,
                                                  const float* __restrict__ sd) {
    int j = blockIdx.x;
    int v0 = blockIdx.y * VCHUNK;
    int v1 = v0 + VCHUNK; if (v1 > V) v1 = V;
    int tid = threadIdx.x;
    const float* jr = Jreg + (size_t)j * V;

    float acc[33];
    #pragma unroll
    for (int e = 0; e < 33; e++) acc[e] = 0.f;

    for (int v = v0 + tid; v < v1; v += 256) {
        float w = jr[v];
        acc[0] += w * vt[v*3 + 0];
        acc[1] += w * vt[v*3 + 1];
        acc[2] += w * vt[v*3 + 2];
        const float2* s2 = reinterpret_cast<const float2*>(sd + (size_t)v*30);
        #pragma unroll
        for (int e = 0; e < 15; e++) {
            float2 sv = s2[e];
            acc[3 + 2*e]     += w * sv.x;
            acc[3 + 2*e + 1] += w * sv.y;
        }
    }

    // warp reduce each of the 33 accumulators
    #pragma unroll
    for (int e = 0; e < 33; e++) {
        float x = acc[e];
        x += __shfl_down_sync(0xffffffffu, x, 16);
        x += __shfl_down_sync(0xffffffffu, x, 8);
        x += __shfl_down_sync(0xffffffffu, x, 4);
        x += __shfl_down_sync(0xffffffffu, x, 2);
        x += __shfl_down_sync(0xffffffffu, x, 1);
        acc[e] = x;
    }
    __shared__ float red[8][33];
    if ((tid & 31) == 0) {
        #pragma unroll
        for (int e = 0; e < 33; e++) red[tid >> 5][e] = acc[e];
    }
    __syncthreads();
    if (tid < 33) {
        float s = 0.f;
        #pragma unroll
        for (int w = 0; w < 8; w++) s += red[w][tid];
        if (tid < 3) atomicAdd(&g_jt[j*3 + tid], s);
        else         atomicAdd(&g_JS[j*30 + (tid - 3)], s);
    }
}

// ---------------------------------------------------------------------------
// K2: rodrigues + chain + rel transforms; fills tf32-rounded g_AT.
// ---------------------------------------------------------------------------
__global__ void k2_pose(const float* __restrict__ ro,
                        const float* __restrict__ pb,
                        const float* __restrict__ ph,
                        const float* __restrict__ betas,
                        const float* __restrict__ trans,
                        float* __restrict__ out_joints) {
    int b = blockIdx.x;
    int lane = threadIdx.x;

    __shared__ float rot[J][9];
    __shared__ float jnt[J][3];
    __shared__ float G[J][12];

    if (lane < J) {
        float r0, r1, r2;
        if (lane == 0)        { const float* p = ro + b*3;                 r0=p[0]; r1=p[1]; r2=p[2]; }
        else if (lane <= 21)  { const float* p = pb + b*63 + (lane-1)*3;   r0=p[0]; r1=p[1]; r2=p[2]; }
        else                  { const float* p = ph + b*6  + (lane-22)*3;  r0=p[0]; r1=p[1]; r2=p[2]; }

        float a2  = r0*r0 + r1*r1 + r2*r2 + 1e-8f;
        float ang = sqrtf(a2);
        float inv = 1.f / ang;
        float x = r0*inv, y = r1*inv, z = r2*inv;
        float c = cosf(ang), s = sinf(ang), o = 1.f - c;

        float R[9];
        R[0] = c + o*x*x;     R[1] = -s*z + o*x*y;  R[2] =  s*y + o*x*z;
        R[3] =  s*z + o*y*x;  R[4] = c + o*y*y;     R[5] = -s*x + o*y*z;
        R[6] = -s*y + o*z*x;  R[7] =  s*x + o*z*y;  R[8] = c + o*z*z;

        #pragma unroll
        for (int e = 0; e < 9; e++) rot[lane][e] = R[e];

        if (lane >= 1) {
            int base = (lane-1)*9;
            #pragma unroll
            for (int e = 0; e < 9; e++)
                g_AT[(base+e)*B + b] = tf32r(R[e] - ((e == 0 || e == 4 || e == 8) ? 1.f : 0.f));
        }

        float bt[NB];
        #pragma unroll
        for (int l = 0; l < NB; l++) bt[l] = betas[b*NB + l];
        #pragma unroll
        for (int k = 0; k < 3; k++) {
            float a = g_jt[lane*3 + k];
            #pragma unroll
            for (int l = 0; l < NB; l++) a += bt[l] * g_JS[lane*30 + k*10 + l];
            jnt[lane][k] = a;
        }
    }
    if (lane < NB)  g_AT[(P + lane)*B + b] = tf32r(betas[b*NB + lane]);
    if (lane >= 25) g_AT[(192 + lane)*B + b] = 0.f;   // rows 217..223
    __syncthreads();

    if (lane == 0) {
        #pragma unroll
        for (int m = 0; m < 3; m++) {
            G[0][m*4+0] = rot[0][m*3+0];
            G[0][m*4+1] = rot[0][m*3+1];
            G[0][m*4+2] = rot[0][m*3+2];
            G[0][m*4+3] = jnt[0][m];
        }
        for (int j = 1; j < J; j++) {
            int p = c_parents[j];
            float t0 = jnt[j][0] - jnt[p][0];
            float t1 = jnt[j][1] - jnt[p][1];
            float t2 = jnt[j][2] - jnt[p][2];
            #pragma unroll
            for (int m = 0; m < 3; m++) {
                float p0 = G[p][m*4+0], p1 = G[p][m*4+1], p2 = G[p][m*4+2], p3 = G[p][m*4+3];
                G[j][m*4+0] = p0*rot[j][0] + p1*rot[j][3] + p2*rot[j][6];
                G[j][m*4+1] = p0*rot[j][1] + p1*rot[j][4] + p2*rot[j][7];
                G[j][m*4+2] = p0*rot[j][2] + p1*rot[j][5] + p2*rot[j][8];
                G[j][m*4+3] = p0*t0 + p1*t1 + p2*t2 + p3;
            }
        }
    }
    __syncthreads();

    if (lane < J) {
        int j = lane;
        float tx = trans[b*3+0], ty = trans[b*3+1], tz = trans[b*3+2];
        float* oj = out_joints + ((size_t)b*J + j)*3;
        oj[0] = G[j][3]  + tx;
        oj[1] = G[j][7]  + ty;
        oj[2] = G[j][11] + tz;

        float* rl = g_rel + ((size_t)b*J + j)*12;
        #pragma unroll
        for (int m = 0; m < 3; m++) {
            float corr = G[j][m*4+0]*jnt[j][0] + G[j][m*4+1]*jnt[j][1] + G[j][m*4+2]*jnt[j][2];
            rl[m*4+0] = G[j][m*4+0];
            rl[m*4+1] = G[j][m*4+1];
            rl[m*4+2] = G[j][m*4+2];
            rl[m*4+3] = G[j][m*4+3] - corr;
        }
    }
}

// ---------------------------------------------------------------------------
// B-row loader for K3: raw fp32 bits (mma.tf32 hardware uses tf32 fields).
// ---------------------------------------------------------------------------
__device__ __forceinline__ void load_B_row(float* dst, int k, int cbase,
                                           const float* __restrict__ posedirs,
                                           const float* __restrict__ sd) {
    if (k < P) {
        if (cbase + 8 <= N3) {
            const float2* s = reinterpret_cast<const float2*>(posedirs + (size_t)k*N3 + cbase);
            #pragma unroll
            for (int i = 0; i < 4; i++) {
                float2 v = s[i];
                dst[2*i]   = v.x;
                dst[2*i+1] = v.y;
            }
        } else {
            #pragma unroll
            for (int i = 0; i < 8; i++) {
                int c = cbase + i;
                dst[i] = (c < N3) ? posedirs[(size_t)k*N3 + c] : 0.f;
            }
        }
    } else if (k < P + NB) {
        int l = k - P;
        #pragma unroll
        for (int i = 0; i < 8; i++) {
            int c = cbase + i;
            dst[i] = (c < N3) ? sd[(size_t)c*NB + l] : 0.f;
        }
    } else {
        #pragma unroll
        for (int i = 0; i < 8; i++) dst[i] = 0.f;
    }
}

// ---------------------------------------------------------------------------
// K3: TF32 GEMM, single-sync double buffer, B loaded direct (R11 measured-best).
// ---------------------------------------------------------------------------
#define BK3 16
#define SST 136
__global__ void __launch_bounds__(256) k3_tf32(const float* __restrict__ vt,
                                               const float* __restrict__ posedirs,
                                               const float* __restrict__ sd) {
    __shared__ float sA[2][BK3][SST];
    __shared__ float sB[2][BK3][SST];

    int tid  = threadIdx.x;
    int warp = tid >> 5, lane = tid & 31;
    int wm = warp >> 2;
    int wn = warp & 3;
    int gr = lane >> 2;
    int tg = lane & 3;

    int c0 = blockIdx.x * 128;
    int b0 = blockIdx.y * 128;

    int lk = tid >> 4;
    int lc = (tid & 15) * 8;

    float acc[4][4][4];
    #pragma unroll
    for (int mi = 0; mi < 4; mi++)
        #pragma unroll
        for (int ni = 0; ni < 4; ni++)
            #pragma unroll
            for (int r = 0; r < 4; r++) acc[mi][ni][r] = 0.f;

    {
        const float4* ga = reinterpret_cast<const float4*>(g_AT + (size_t)lk*B + b0 + lc);
        float bv[8];
        load_B_row(bv, lk, c0 + lc, posedirs, sd);
        float4 a0 = ga[0], a1 = ga[1];
        *reinterpret_cast<float4*>(&sA[0][lk][lc])     = a0;
        *reinterpret_cast<float4*>(&sA[0][lk][lc + 4]) = a1;
        *reinterpret_cast<float4*>(&sB[0][lk][lc])     = *reinterpret_cast<float4*>(bv);
        *reinterpret_cast<float4*>(&sB[0][lk][lc + 4]) = *reinterpret_cast<float4*>(bv + 4);
    }
    __syncthreads();

    const int NST = KT / BK3;    // 14
    for (int st = 0; st < NST; st++) {
        float4 pa0, pa1;
        float pbv[8];
        bool has_next = (st + 1 < NST);
        if (has_next) {
            int k = (st + 1) * BK3 + lk;
            const float4* ga = reinterpret_cast<const float4*>(g_AT + (size_t)k*B + b0 + lc);
            pa0 = ga[0]; pa1 = ga[1];
            load_B_row(pbv, k, c0 + lc, posedirs, sd);
        }
        int buf = st & 1;

        #pragma unroll
        for (int ks = 0; ks < 2; ks++) {
            int kb = ks * 8;
            uint32_t bfr[4][2];
            #pragma unroll
            for (int ni = 0; ni < 4; ni++) {
                int n = wn*32 + ni*8 + gr;
                bfr[ni][0] = __float_as_uint(sB[buf][kb + tg][n]);
                bfr[ni][1] = __float_as_uint(sB[buf][kb + tg + 4][n]);
            }
            uint32_t afr[4][4];
            #pragma unroll
            for (int mi = 0; mi < 4; mi++) {
                int m = wm*64 + mi*16 + gr;
                afr[mi][0] = __float_as_uint(sA[buf][kb + tg][m]);
                afr[mi][1] = __float_as_uint(sA[buf][kb + tg][m + 8]);
                afr[mi][2] = __float_as_uint(sA[buf][kb + tg + 4][m]);
                afr[mi][3] = __float_as_uint(sA[buf][kb + tg + 4][m + 8]);
            }
            #pragma unroll
            for (int mi = 0; mi < 4; mi++)
                #pragma unroll
                for (int ni = 0; ni < 4; ni++)
                    MMA_TF32(acc[mi][ni], afr[mi][0], afr[mi][1], afr[mi][2], afr[mi][3],
                             bfr[ni][0], bfr[ni][1]);
        }

        if (has_next) {
            int nb = 1 - buf;
            *reinterpret_cast<float4*>(&sA[nb][lk][lc])     = pa0;
            *reinterpret_cast<float4*>(&sA[nb][lk][lc + 4]) = pa1;
            *reinterpret_cast<float4*>(&sB[nb][lk][lc])     = *reinterpret_cast<float4*>(pbv);
            *reinterpret_cast<float4*>(&sB[nb][lk][lc + 4]) = *reinterpret_cast<float4*>(pbv + 4);
            __syncthreads();
        }
    }

    #pragma unroll
    for (int mi = 0; mi < 4; mi++) {
        #pragma unroll
        for (int half = 0; half < 2; half++) {
            int b = b0 + wm*64 + mi*16 + gr + half*8;
            #pragma unroll
            for (int ni = 0; ni < 4; ni++) {
                int c = c0 + wn*32 + ni*8 + tg*2;
                float v0 = (c     < N3) ? vt[c]     : 0.f;
                float v1 = (c + 1 < N3) ? vt[c + 1] : 0.f;
                float2 o = make_float2(acc[mi][ni][half*2]     + v0,
                                       acc[mi][ni][half*2 + 1] + v1);
                *reinterpret_cast<float2*>(g_vposed + (size_t)b*VS + c) = o;
            }
        }
    }
}

// ---------------------------------------------------------------------------
// K4: scalar skinning (measured 61-62us, regs 80, fma 48% = scalar ceiling).
// ---------------------------------------------------------------------------
__global__ void __launch_bounds__(256) k4_skin(const float* __restrict__ weights,
                                               const float* __restrict__ trans,
                                               float* __restrict__ out) {
    int tid = threadIdx.x;        // 256 = 8 warps
    int warp = tid >> 5;
    int lane = tid & 31;
    int b = blockIdx.y * 8 + warp;

    __shared__ float4 s_rel[8][J*3];
    {
        const float4* src = reinterpret_cast<const float4*>(g_rel);
        for (int i = tid; i < 8*J*3; i += 256) {
            int bl = i / (J*3), e = i % (J*3);
            s_rel[bl][e] = src[(size_t)(blockIdx.y*8 + bl)*(J*3) + e];
        }
    }
    __syncthreads();

    float t0 = trans[b*3+0], t1 = trans[b*3+1], t2 = trans[b*3+2];
    const float4* rel = s_rel[warp];
    const size_t bbase = (size_t)b * VS;

    int v0 = blockIdx.x * 128;
    int v[4]; bool ok[4];
    float vx[4], vy[4], vz[4], ox[4], oy[4], oz[4];
    #pragma unroll
    for (int u = 0; u < 4; u++) {
        int vv = v0 + u*32 + lane;
        ok[u] = vv < V;
        v[u] = ok[u] ? vv : (V - 1);
        vx[u] = g_vposed[bbase + v[u]*3 + 0];
        vy[u] = g_vposed[bbase + v[u]*3 + 1];
        vz[u] = g_vposed[bbase + v[u]*3 + 2];
        ox[u] = t0; oy[u] = t1; oz[u] = t2;
    }

    const float4* wv0 = reinterpret_cast<const float4*>(weights + (size_t)v[0]*J);
    const float4* wv1 = reinterpret_cast<const float4*>(weights + (size_t)v[1]*J);
    const float4* wv2 = reinterpret_cast<const float4*>(weights + (size_t)v[2]*J);
    const float4* wv3 = reinterpret_cast<const float4*>(weights + (size_t)v[3]*J);

    #pragma unroll
    for (int q = 0; q < 6; q++) {
        float4 w[4];
        w[0] = wv0[q]; w[1] = wv1[q]; w[2] = wv2[q]; w[3] = wv3[q];
        #pragma unroll
        for (int jj = 0; jj < 4; jj++) {
            int j = q*4 + jj;
            float4 r0 = rel[j*3 + 0];
            float4 r1 = rel[j*3 + 1];
            float4 r2 = rel[j*3 + 2];
            #pragma unroll
            for (int u = 0; u < 4; u++) {
                float wj = (jj == 0) ? w[u].x : (jj == 1) ? w[u].y : (jj == 2) ? w[u].z : w[u].w;
                float rx = fmaf(r0.x, vx[u], fmaf(r0.y, vy[u], fmaf(r0.z, vz[u], r0.w)));
                float ry = fmaf(r1.x, vx[u], fmaf(r1.y, vy[u], fmaf(r1.z, vz[u], r1.w)));
                float rz = fmaf(r2.x, vx[u], fmaf(r2.y, vy[u], fmaf(r2.z, vz[u], r2.w)));
                ox[u] = fmaf(wj, rx, ox[u]);
                oy[u] = fmaf(wj, ry, oy[u]);
                oz[u] = fmaf(wj, rz, oz[u]);
            }
        }
    }

    #pragma unroll
    for (int u = 0; u < 4; u++) {
        if (ok[u]) {
            float* o = out + ((size_t)b*V + v[u])*3;
            o[0] = ox[u]; o[1] = oy[u]; o[2] = oz[u];
        }
    }
}

// ---------------------------------------------------------------------------
extern "C" void kernel_launch(void* const* d_in, const int* in_sizes, int n_in,
                              void* d_out, int out_size) {
    const float* root_orient = (const float*)d_in[0];
    const float* pose_body   = (const float*)d_in[1];
    const float* pose_hand   = (const float*)d_in[2];
    const float* betas       = (const float*)d_in[3];
    const float* trans       = (const float*)d_in[4];
    const float* v_template  = (const float*)d_in[5];
    const float* shapedirs   = (const float*)d_in[6];
    const float* posedirs    = (const float*)d_in[7];
    const float* J_regressor = (const float*)d_in[8];
    const float* weights     = (const float*)d_in[9];

    float* out = (float*)d_out;
    float* out_joints = out + (size_t)B * V * 3;

    k0_zero<<<3, 256>>>();
    k1_regress<<<dim3(J, 8), 256>>>(J_regressor, v_template, shapedirs);
    k2_pose<<<B, 32>>>(root_orient, pose_body, pose_hand, betas, trans, out_joints);
    k3_tf32<<<dim3(VS/128, B/128), 256>>>(v_template, posedirs, shapedirs);
    k4_skin<<<dim3((V + 127)/128, B/8), 256>>>(weights, trans, out);
}